// round 9
// baseline (speedup 1.0000x reference)
#include <cuda_runtime.h>
#include <cstdint>

#define N_ANCH 36864
#define PRE    6000
#define NWORDS 94      /* ceil(6000/64) */
#define POST   300
#define NMS_T  0.7f
#define NEG_INF_F (-1e9f)
#define NBINS  65536
#define BPT    64      /* bins per thread (65536/1024) */

// ---------------- scratch (static device globals; no allocation) ----------------
__device__ float4             g_boxes[N_ANCH];          // decoded+clipped boxes
__device__ unsigned long long g_keyfull[N_ANCH];        // (desc<<16)|idx
__device__ int                g_hist[NBINS];            // zero at load; re-zeroed each run
__device__ int                g_bin_base[NBINS];
__device__ int                g_bin_fill[NBINS];        // zero at load; re-zeroed each run
__device__ unsigned long long g_cand[N_ANCH];
__device__ float4             g_boxes_s[PRE];           // top-6000 boxes, score order

// ---------------- 1. decode + clip + valid + key + histogram ----------------
__global__ void decode_kernel(const float4* __restrict__ anchors,
                              const float* __restrict__ cls,
                              const float4* __restrict__ reg,
                              const int* __restrict__ img_w_p,
                              const int* __restrict__ img_h_p,
                              int have_wh)
{
    int i = blockIdx.x * blockDim.x + threadIdx.x;
    if (i >= N_ANCH) return;

    float4 a = anchors[i];
    float4 r = reg[i];

    float w  = __fsub_rn(a.z, a.x);
    float h  = __fsub_rn(a.w, a.y);
    float cx = __fadd_rn(a.x, __fmul_rn(0.5f, w));
    float cy = __fadd_rn(a.y, __fmul_rn(0.5f, h));
    float pcx = __fadd_rn(__fmul_rn(r.x, w), cx);
    float pcy = __fadd_rn(__fmul_rn(r.y, h), cy);
    float pw  = __fmul_rn(expf(r.z), w);
    float ph  = __fmul_rn(expf(r.w), h);

    float b0 = __fsub_rn(pcx, __fmul_rn(0.5f, pw));
    float b1 = __fsub_rn(pcy, __fmul_rn(0.5f, ph));
    float b2 = __fadd_rn(pcx, __fmul_rn(0.5f, pw));
    float b3 = __fadd_rn(pcy, __fmul_rn(0.5f, ph));

    float H = have_wh ? (float)(*img_h_p) : 1024.0f;
    float W = have_wh ? (float)(*img_w_p) : 1024.0f;
    // reference: cols 0,2 clipped by img_h; cols 1,3 by img_w
    b0 = fminf(fmaxf(b0, 0.0f), H);
    b2 = fminf(fmaxf(b2, 0.0f), H);
    b1 = fminf(fmaxf(b1, 0.0f), W);
    b3 = fminf(fmaxf(b3, 0.0f), W);

    bool valid = (__fsub_rn(b2, b0) >= 16.0f) && (__fsub_rn(b3, b1) >= 16.0f);
    float s = valid ? cls[i] : NEG_INF_F;

    g_boxes[i] = make_float4(b0, b1, b2, b3);

    // stable descending sort key: smaller desc = higher score; idx breaks ties (stable)
    unsigned int bits = __float_as_uint(s);
    unsigned int asc  = (bits & 0x80000000u) ? ~bits : (bits | 0x80000000u);
    unsigned int desc = ~asc;
    unsigned long long key = ((unsigned long long)desc << 16) | (unsigned int)i;
    g_keyfull[i] = key;
    atomicAdd(&g_hist[desc >> 16], 1);
}

// ---------------- 2. fused select (plan+scatter+rank) + greedy NMS ----------------
__device__ __forceinline__ int iou_gt(float4 a, float aa, float4 b, float ab)
{
    float xx1 = fmaxf(a.x, b.x);
    float yy1 = fmaxf(a.y, b.y);
    float xx2 = fminf(a.z, b.z);
    float yy2 = fminf(a.w, b.w);
    float iw  = fmaxf(__fsub_rn(xx2, xx1), 0.0f);
    float ih  = fmaxf(__fsub_rn(yy2, yy1), 0.0f);
    float inter = __fmul_rn(iw, ih);
    // exact reference op order: ((aa + ab) - inter) + 1e-9, IEEE divide
    float den = __fadd_rn(__fsub_rn(__fadd_rn(aa, ab), inter), 1e-9f);
    float iou = __fdiv_rn(inter, den);
    return iou > NMS_T;
}

__global__ void __launch_bounds__(1024) select_nms_kernel(float* __restrict__ out)
{
    __shared__ int sp[1024];
    __shared__ int s_thresh;
    __shared__ int s_cand_total;
    __shared__ unsigned long long s_invalid[NWORDS];   // pre-suppressed (invalid/tail) bits
    __shared__ float4            s_kb[POST];           // kept boxes, score order
    __shared__ float             s_ka[POST];
    __shared__ float4            s_cb[64];
    __shared__ float             s_ca[64];
    __shared__ unsigned long long s_intra[64];
    __shared__ unsigned long long s_sup;
    __shared__ int s_kept;

    int t = threadIdx.x;

    // ---- phase 1: plan (prefix-sum 65536 bins, find threshold bin) ----
    if (t == 0) { s_thresh = 0x7FFFFFFF; s_kept = 0; }
    if (t < NWORDS)
        s_invalid[t] = (t == NWORDS-1) ? ~((1ull << 48) - 1) : 0ull;   // ranks >= 6000

    int b0 = t * BPT;
    int sum = 0;
    for (int k = 0; k < BPT; k++) { sum += g_hist[b0 + k]; g_bin_fill[b0 + k] = 0; }
    sp[t] = sum;
    __syncthreads();
    for (int off = 1; off < 1024; off <<= 1) {
        int v = (t >= off) ? sp[t - off] : 0;
        __syncthreads();
        sp[t] += v;
        __syncthreads();
    }
    int run = sp[t] - sum;                 // exclusive prefix for this thread's range
    bool straddle = (run < PRE) && (sp[t] >= PRE);
    for (int k = 0; k < BPT; k++) {
        int h = g_hist[b0 + k];            // re-read (L2 hit)
        g_bin_base[b0 + k] = run;
        run += h;
        if (straddle && run >= PRE && run - h < PRE) atomicMin(&s_thresh, b0 + k);
    }
    __syncthreads();
    if (t == 0) s_cand_total = g_bin_base[s_thresh] + g_hist[s_thresh];
    __syncthreads();

    // ---- phase 2: scatter candidates into per-bin segments ----
    int thresh = s_thresh;
    for (int i = t; i < N_ANCH; i += 1024) {
        unsigned long long key = g_keyfull[i];
        int bin = (int)(key >> 32);
        if (bin <= thresh) {
            int pos = g_bin_base[bin] + atomicAdd(&g_bin_fill[bin], 1);
            g_cand[pos] = key;
        }
    }
    __syncthreads();

    // ---- phase 3: exact rank within bin + gather boxes ----
    int tot = s_cand_total;
    for (int c = t; c < tot; c += 1024) {
        unsigned long long key = g_cand[c];
        int bin = (int)(key >> 32);
        int s0 = g_bin_base[bin];
        int s1 = s0 + g_bin_fill[bin];
        int rank = s0;
        for (int j = s0; j < s1; j++)
            if (g_cand[j] < key) rank++;
        if (rank < PRE) {
            int idx = (int)(key & 0xFFFFull);
            g_boxes_s[rank] = g_boxes[idx];
            unsigned int desc = (unsigned int)(key >> 16);
            if (desc & 0x80000000u)   // invalid box -> pre-suppressed
                atomicOr(&s_invalid[rank >> 6], 1ull << (rank & 63));
        }
    }
    // re-zero histogram for the next graph replay (decode re-accumulates)
    for (int k = 0; k < BPT; k++) g_hist[b0 + k] = 0;
    __syncthreads();

    // ---- phase 4: greedy NMS, chunked by 64 ranks, on-the-fly IoU ----
    for (int c = 0; c < NWORDS; c++) {
        if (t < 64) {
            int i = c * 64 + t;
            float4 b = (i < PRE) ? g_boxes_s[i] : make_float4(0.f, 0.f, 0.f, 0.f);
            s_cb[t] = b;
            s_ca[t] = __fmul_rn(__fsub_rn(b.z, b.x), __fsub_rn(b.w, b.y));
            s_intra[t] = 0ull;
        }
        if (t == 1023) s_sup = 0ull;
        int kept0 = s_kept;
        __syncthreads();

        // A) chunk vs already-kept
        for (int p = t; p < 64 * kept0; p += 1024) {
            int b = p & 63;
            int k = p >> 6;
            if (iou_gt(s_kb[k], s_ka[k], s_cb[b], s_ca[b]))
                atomicOr(&s_sup, 1ull << b);
        }
        // B) intra-chunk upper triangle
        for (int p = t; p < 64 * 64; p += 1024) {
            int i = p >> 6;
            int j = p & 63;
            if (j > i && iou_gt(s_cb[i], s_ca[i], s_cb[j], s_ca[j]))
                atomicOr(&s_intra[i], 1ull << j);
        }
        __syncthreads();

        // C) serial greedy walk
        if (t == 0) {
            unsigned long long rem = s_invalid[c] | s_sup;
            int kept = kept0;
            unsigned long long m = ~rem;
            while (m) {
                int b = __ffsll((long long)m) - 1;
                s_kb[kept] = s_cb[b];
                s_ka[kept] = s_ca[b];
                kept++;
                if (kept >= POST) break;
                rem |= s_intra[b];
                m = ~rem & (~0ull << (b + 1));
            }
            s_kept = kept;
        }
        __syncthreads();
        if (s_kept >= POST) break;                   // output fixed
    }
    __syncthreads();

    // ---- output: kept boxes in order, zero-pad tail ----
    int kept = s_kept;
    if (t < POST) {
        float4 v = make_float4(0.f, 0.f, 0.f, 0.f);
        if (t < kept) v = s_kb[t];
        reinterpret_cast<float4*>(out)[t] = v;
    }
}

// ---------------- launch ----------------
extern "C" void kernel_launch(void* const* d_in, const int* in_sizes, int n_in,
                              void* d_out, int out_size)
{
    const float4* anchors = (const float4*)d_in[0];
    const float*  cls     = (const float*)d_in[1];
    const float4* reg     = (const float4*)d_in[2];
    const int*    img_w   = (n_in > 3) ? (const int*)d_in[3] : nullptr;
    const int*    img_h   = (n_in > 4) ? (const int*)d_in[4] : nullptr;
    int have_wh = (n_in > 4) ? 1 : 0;

    decode_kernel<<<(N_ANCH + 255) / 256, 256>>>(anchors, cls, reg, img_w, img_h, have_wh);
    select_nms_kernel<<<1, 1024>>>((float*)d_out);
}

// round 10
// speedup vs baseline: 3.8830x; 3.8830x over previous
#include <cuda_runtime.h>
#include <cstdint>

#define N_ANCH 36864
#define PRE    6000
#define POST   300
#define NMS_T  0.7f
#define NEG_INF_F (-1e9f)
#define TOPK   1024
#define CAP    2048
#define MAX_ROUNDS 16

typedef unsigned long long u64;

// ---------------- scratch (static device globals; no allocation) ----------------
__device__ float4 g_boxes[N_ANCH];     // decoded+clipped boxes
__device__ u64    g_keys[N_ANCH];      // (desc<<16)|idx  (unique: idx in low 16 bits)
__device__ int    g_hist_lo[65536];    // fine hist (desc>>16); zeroed by clear_kernel
__device__ int    g_hist_hi[256];      // coarse hist (desc>>24)

// ---------------- 1. decode + clip + valid + key + 2-level histogram ----------------
__global__ void decode_kernel(const float4* __restrict__ anchors,
                              const float* __restrict__ cls,
                              const float4* __restrict__ reg,
                              const int* __restrict__ img_w_p,
                              const int* __restrict__ img_h_p,
                              int have_wh)
{
    __shared__ int sh_hi[256];
    int tid = threadIdx.x;                      // blockDim == 256
    sh_hi[tid] = 0;
    __syncthreads();

    int i = blockIdx.x * 256 + tid;             // grid exact: 144*256 == N_ANCH

    float4 a = anchors[i];
    float4 r = reg[i];

    float w  = __fsub_rn(a.z, a.x);
    float h  = __fsub_rn(a.w, a.y);
    float cx = __fadd_rn(a.x, __fmul_rn(0.5f, w));
    float cy = __fadd_rn(a.y, __fmul_rn(0.5f, h));
    float pcx = __fadd_rn(__fmul_rn(r.x, w), cx);
    float pcy = __fadd_rn(__fmul_rn(r.y, h), cy);
    float pw  = __fmul_rn(expf(r.z), w);
    float ph  = __fmul_rn(expf(r.w), h);

    float b0 = __fsub_rn(pcx, __fmul_rn(0.5f, pw));
    float b1 = __fsub_rn(pcy, __fmul_rn(0.5f, ph));
    float b2 = __fadd_rn(pcx, __fmul_rn(0.5f, pw));
    float b3 = __fadd_rn(pcy, __fmul_rn(0.5f, ph));

    float H = have_wh ? (float)(*img_h_p) : 1024.0f;
    float W = have_wh ? (float)(*img_w_p) : 1024.0f;
    // reference: cols 0,2 clipped by img_h; cols 1,3 by img_w
    b0 = fminf(fmaxf(b0, 0.0f), H);
    b2 = fminf(fmaxf(b2, 0.0f), H);
    b1 = fminf(fmaxf(b1, 0.0f), W);
    b3 = fminf(fmaxf(b3, 0.0f), W);

    bool valid = (__fsub_rn(b2, b0) >= 16.0f) && (__fsub_rn(b3, b1) >= 16.0f);
    float s = valid ? cls[i] : NEG_INF_F;

    g_boxes[i] = make_float4(b0, b1, b2, b3);

    // stable descending key: smaller key = higher score; idx breaks ties (stable)
    unsigned int bits = __float_as_uint(s);
    unsigned int asc  = (bits & 0x80000000u) ? ~bits : (bits | 0x80000000u);
    unsigned int desc = ~asc;
    u64 key = ((u64)desc << 16) | (unsigned int)i;
    g_keys[i] = key;

    atomicAdd(&g_hist_lo[(int)(key >> 32)], 1);           // desc>>16
    atomicAdd(&sh_hi[(int)((key >> 40) & 255)], 1);       // desc>>24 (block-aggregated)
    __syncthreads();
    if (sh_hi[tid]) atomicAdd(&g_hist_hi[tid], sh_hi[tid]);
}

// ---------------- IoU predicate (exact reference op order) ----------------
__device__ __forceinline__ int iou_gt(float4 a, float aa, float4 b, float ab)
{
    float xx1 = fmaxf(a.x, b.x);
    float yy1 = fmaxf(a.y, b.y);
    float xx2 = fminf(a.z, b.z);
    float yy2 = fminf(a.w, b.w);
    float iw  = fmaxf(__fsub_rn(xx2, xx1), 0.0f);
    float ih  = fmaxf(__fsub_rn(yy2, yy1), 0.0f);
    float inter = __fmul_rn(iw, ih);
    float den = __fadd_rn(__fsub_rn(__fadd_rn(aa, ab), inter), 1e-9f);
    float iou = __fdiv_rn(inter, den);
    return iou > NMS_T;
}

// ---------------- 2. rounds of (plan -> scatter -> shared sort -> NMS) ----------------
__global__ void __launch_bounds__(1024) select_nms_kernel(float* __restrict__ out)
{
    __shared__ u64    s_cand[CAP];      // candidate keys (sorted ascending = rank order)
    __shared__ float4 s_kb[POST];       // kept boxes, score order
    __shared__ float  s_ka[POST];
    __shared__ float4 s_cb[64];
    __shared__ float  s_ca[64];
    __shared__ u64    s_intra[64];
    __shared__ u64    s_sup;
    __shared__ int    s_scan[256];
    __shared__ int    s_H, s_baseH, s_thresh, s_ctr, s_kept;

    int t = threadIdx.x;
    if (t == 0) s_kept = 0;

    u64 last_key = 0;                   // exclusive lower bound of processed keys
    int processed = 0;                  // global ranks already processed
    bool done = false;

    for (int round = 0; round < MAX_ROUNDS && !done; round++) {
        // ---- plan: coarse scan ----
        if (t == 0) { s_H = 0; s_baseH = 0; s_thresh = 0; s_ctr = 0; }
        if (t < 256) s_scan[t] = g_hist_hi[t];
        __syncthreads();
        for (int off = 1; off < 256; off <<= 1) {
            int v = 0;
            if (t < 256 && t >= off) v = s_scan[t - off];
            __syncthreads();
            if (t < 256) s_scan[t] += v;
            __syncthreads();
        }
        int total = s_scan[255];
        if (processed >= PRE || processed >= total) break;
        int target = (round + 1) * TOPK;
        if (target > total) target = total;
        if (processed >= target) continue;        // empty round; target grows next
        if (t < 256) {
            int incl = s_scan[t];
            int excl = t ? s_scan[t - 1] : 0;
            if (excl < target && incl >= target) { s_H = t; s_baseH = excl; }
        }
        __syncthreads();
        int Hb = s_H, baseH = s_baseH;

        // ---- plan: fine scan within coarse bin Hb ----
        if (t < 256) s_scan[t] = g_hist_lo[Hb * 256 + t];
        __syncthreads();
        for (int off = 1; off < 256; off <<= 1) {
            int v = 0;
            if (t < 256 && t >= off) v = s_scan[t - off];
            __syncthreads();
            if (t < 256) s_scan[t] += v;
            __syncthreads();
        }
        if (t < 256) {
            int incl = baseH + s_scan[t];
            int excl = baseH + (t ? s_scan[t - 1] : 0);
            if (excl < target && incl >= target) s_thresh = Hb * 256 + t;
        }
        __syncthreads();
        int thresh = s_thresh;

        // ---- scatter candidates: keys in (last_key, thresh-bin end] ----
        for (int i = t; i < N_ANCH; i += 1024) {
            u64 k = g_keys[i];
            if (k > last_key && (int)(k >> 32) <= thresh) {
                int p = atomicAdd(&s_ctr, 1);
                if (p < CAP) s_cand[p] = k;
            }
        }
        __syncthreads();
        int ctr = s_ctr;

        if (ctr > CAP) {
            // pathological mass-tie case (keys unique -> count steps by 1; never runs on
            // benchmark data). Bisect key space for largest cut with count <= CAP.
            u64 cur = last_key;
            for (int b = 63; b >= 0; b--) {
                u64 try_cut = cur | (1ull << b);
                if (try_cut == cur) continue;
                int local = 0;
                for (int i = t; i < N_ANCH; i += 1024) {
                    u64 k = g_keys[i];
                    if (k > last_key && k <= try_cut) local++;
                }
                if (t == 0) s_ctr = 0;
                __syncthreads();
                atomicAdd(&s_ctr, local);
                __syncthreads();
                if (s_ctr <= CAP) cur = try_cut;
                __syncthreads();
            }
            if (t == 0) s_ctr = 0;
            __syncthreads();
            for (int i = t; i < N_ANCH; i += 1024) {
                u64 k = g_keys[i];
                if (k > last_key && k <= cur) {
                    int p = atomicAdd(&s_ctr, 1);
                    s_cand[p] = k;
                }
            }
            __syncthreads();
            ctr = s_ctr;
        }
        if (ctr == 0) continue;

        // ---- pad + bitonic sort (ascending = score-descending rank order) ----
        for (int p = ctr + t; p < CAP; p += 1024) s_cand[p] = ~0ull;
        __syncthreads();
        for (int k = 2; k <= CAP; k <<= 1) {
            for (int j = k >> 1; j > 0; j >>= 1) {
                int i   = ((t & ~(j - 1)) << 1) | (t & (j - 1));
                int ixj = i | j;
                bool up = ((i & k) == 0);
                u64 x = s_cand[i], y = s_cand[ixj];
                if (up ? (x > y) : (x < y)) { s_cand[i] = y; s_cand[ixj] = x; }
                __syncthreads();
            }
        }

        // ---- NMS over this round's ranks, chunked by 64 ----
        int n_this = ctr;
        if (n_this > PRE - processed) n_this = PRE - processed;   // rank cap at 6000
        int nchunks = (n_this + 63) >> 6;
        for (int c = 0; c < nchunks; c++) {
            if (t == 0) s_sup = 0ull;
            __syncthreads();
            if (t < 64) {
                int pos = c * 64 + t;
                u64 k = s_cand[pos];
                bool live = (pos < n_this) && !((k >> 47) & 1);   // rank-capped or invalid
                float4 b = live ? g_boxes[(int)(k & 0xFFFFull)]
                                : make_float4(0.f, 0.f, 0.f, 0.f);
                s_cb[t] = b;
                s_ca[t] = __fmul_rn(__fsub_rn(b.z, b.x), __fsub_rn(b.w, b.y));
                s_intra[t] = 0ull;
                if (!live) atomicOr(&s_sup, 1ull << t);
            }
            int kept0 = s_kept;
            __syncthreads();

            // A) chunk vs already-kept
            for (int p = t; p < 64 * kept0; p += 1024) {
                int b = p & 63;
                int k2 = p >> 6;
                if (iou_gt(s_kb[k2], s_ka[k2], s_cb[b], s_ca[b]))
                    atomicOr(&s_sup, 1ull << b);
            }
            // B) intra-chunk upper triangle
            for (int p = t; p < 4096; p += 1024) {
                int i2 = p >> 6;
                int j2 = p & 63;
                if (j2 > i2 && iou_gt(s_cb[i2], s_ca[i2], s_cb[j2], s_ca[j2]))
                    atomicOr(&s_intra[i2], 1ull << j2);
            }
            __syncthreads();

            // C) serial greedy walk
            if (t == 0) {
                u64 rem = s_sup;
                int kept = kept0;
                u64 m = ~rem;
                while (m) {
                    int b = __ffsll((long long)m) - 1;
                    s_kb[kept] = s_cb[b];
                    s_ka[kept] = s_ca[b];
                    kept++;
                    if (kept >= POST) break;
                    rem |= s_intra[b];
                    m = ~rem & (~0ull << (b + 1));
                }
                s_kept = kept;
            }
            __syncthreads();
            if (s_kept >= POST) { done = true; break; }
        }
        if (done) break;
        processed += ctr;
        if (n_this < ctr) break;                 // hit rank-6000 cap
        last_key = s_cand[ctr - 1];              // largest processed key (uniform read)
        __syncthreads();
    }
    __syncthreads();

    // ---- output: kept boxes in order, zero-pad tail ----
    int kept = s_kept;
    if (t < POST) {
        float4 v = make_float4(0.f, 0.f, 0.f, 0.f);
        if (t < kept) v = s_kb[t];
        reinterpret_cast<float4*>(out)[t] = v;
    }
}

// ---------------- 3. grid-wide histogram clear (for next graph replay) ----------------
__global__ void clear_kernel()
{
    int i = blockIdx.x * blockDim.x + threadIdx.x;
    g_hist_lo[i] = 0;                            // grid exact: 64*1024 == 65536
    if (i < 256) g_hist_hi[i] = 0;
}

// ---------------- launch ----------------
extern "C" void kernel_launch(void* const* d_in, const int* in_sizes, int n_in,
                              void* d_out, int out_size)
{
    const float4* anchors = (const float4*)d_in[0];
    const float*  cls     = (const float*)d_in[1];
    const float4* reg     = (const float4*)d_in[2];
    const int*    img_w   = (n_in > 3) ? (const int*)d_in[3] : nullptr;
    const int*    img_h   = (n_in > 4) ? (const int*)d_in[4] : nullptr;
    int have_wh = (n_in > 4) ? 1 : 0;

    decode_kernel<<<N_ANCH / 256, 256>>>(anchors, cls, reg, img_w, img_h, have_wh);
    select_nms_kernel<<<1, 1024>>>((float*)d_out);
    clear_kernel<<<64, 1024>>>();
}